// round 5
// baseline (speedup 1.0000x reference)
#include <cuda_runtime.h>
#include <math.h>
#include <float.h>
#include <stdint.h>

#define BATCH 8
#define CH    256
#define NH    9
#define S     48
#define SP    (S*S)        // 2304
#define HD    (NH*CH)      // 2304
#define NSPAT (BATCH*SP)   // 18432

typedef unsigned long long ull;

// f32x2 packed helpers
#define FMA2(d,a,b)  asm("fma.rn.f32x2 %0, %1, %2, %0;" : "+l"(d) : "l"(a), "l"(b))
#define PACK2(d,x,y) asm("mov.b64 %0, {%1,%2};" : "=l"(d) : "f"(x), "f"(y))
#define DUP2(d,x)    asm("mov.b64 %0, {%1,%1};" : "=l"(d) : "f"(x))
#define UNPK2(x,y,d) asm("mov.b64 {%0,%1}, %2;" : "=f"(x), "=f"(y) : "l"(d))

// Scratch (static __device__ — no allocations allowed)
__device__ float d_g1 [NH][S][S];   // [h][i][k]
__device__ float d_g2 [NH][S][S];   // [h][j][l]
__device__ float d_g1t[NH][S][S];   // [h][k][i]
__device__ float d_g2t[NH][S][S];   // [h][l][j]
__device__ float d_U[HD][NSPAT];    // [hd][b*2304 + j*48 + i]

// ---------------------------------------------------------------------------
// Kernel 0: per-row 1D Gaussian softmax factors (and transposes)
// ---------------------------------------------------------------------------
__global__ void k_gauss(const float* __restrict__ centers,
                        const float* __restrict__ spreads) {
    int gw   = (blockIdx.x * blockDim.x + threadIdx.x) >> 5;
    int lane = threadIdx.x & 31;
    if (gw >= 2 * NH * S) return;
    int which = gw / (NH * S);
    int r     = gw % (NH * S);
    int h = r / S, pos = r % S;
    float sp = spreads[h];
    float a  = sp * sp;
    float mu = centers[2 * h + which];

    float dx0 = (float)(lane - pos);
    float e0  = a * (mu * dx0 - 0.5f * dx0 * dx0);
    float e1  = -FLT_MAX;
    if (lane < S - 32) {
        float dx1 = (float)(lane + 32 - pos);
        e1 = a * (mu * dx1 - 0.5f * dx1 * dx1);
    }
    float m = fmaxf(e0, e1);
    #pragma unroll
    for (int o = 16; o > 0; o >>= 1) m = fmaxf(m, __shfl_xor_sync(0xffffffffu, m, o));
    float v0 = expf(e0 - m);
    float v1 = (lane < S - 32) ? expf(e1 - m) : 0.f;
    float s = v0 + v1;
    #pragma unroll
    for (int o = 16; o > 0; o >>= 1) s += __shfl_xor_sync(0xffffffffu, s, o);
    float inv = 1.f / s;
    v0 *= inv; v1 *= inv;

    float (*g )[S] = which ? d_g2 [h] : d_g1 [h];
    float (*gt)[S] = which ? d_g2t[h] : d_g1t[h];
    g [pos][lane] = v0;
    gt[lane][pos] = v0;
    if (lane < S - 32) {
        g [pos][lane + 32] = v1;
        gt[lane + 32][pos] = v1;
    }
}

// ---------------------------------------------------------------------------
// Kernel 1: probs[i,j,h,k,l] = P1[h,i,k] * P2[h,j,l]   (pure HBM write)
// ---------------------------------------------------------------------------
__global__ __launch_bounds__(192) void k_probs(float* __restrict__ probs) {
    int blk = blockIdx.x;
    int h   = blk % NH;
    int ij  = blk / NH;
    int j = ij % S, i = ij / S;
    __shared__ float f[S];
    __shared__ float g[S];
    int t = threadIdx.x;
    if (t < S)            f[t]     = d_g1[h][i][t];
    else if (t < 2 * S)   g[t - S] = d_g2[h][j][t - S];
    __syncthreads();
    float4* outp = (float4*)(probs + (size_t)blk * SP);
    const float4* g4 = (const float4*)g;
    #pragma unroll
    for (int q = t; q < SP / 4; q += 192) {
        int k = q / 12, l4 = q % 12;
        float  fk = f[k];
        float4 gv = g4[l4];
        outp[q] = make_float4(fk * gv.x, fk * gv.y, fk * gv.z, fk * gv.w);
    }
}

// ---------------------------------------------------------------------------
// Fused stages A+B (unchanged from R4 — validated)
// ---------------------------------------------------------------------------
__global__ __launch_bounds__(288) void k_fusedAB(const float* __restrict__ hs) {
    __shared__ float Xs[2][SP];   // [slab][l*48 + k]
    __shared__ float Ts[2][SP];   // [slab][j*48 + k]
    __shared__ float Gs[SP];      // g2t[l*48+j] then g1t[k*48+i]
    int blk = blockIdx.x;
    int b  = blk >> 7;
    int dp = blk & 127;
    int t  = threadIdx.x;
    int slab = t / 144, tt = t % 144;
    int tk = tt % 12, tj = tt / 12;
    {
        const float4* src = (const float4*)(hs + (size_t)(b * CH + dp * 2) * SP);
        float4* dst = (float4*)&Xs[0][0];
        for (int q = t; q < 2 * SP / 4; q += 288) dst[q] = src[q];
    }
    for (int h = 0; h < NH; h++) {
        __syncthreads();
        {
            const float4* gsrc = (const float4*)&d_g2t[h][0][0];
            float4* gdst = (float4*)Gs;
            for (int q = t; q < SP / 4; q += 288) gdst[q] = gsrc[q];
        }
        __syncthreads();
        ull acc1[4][2];
        #pragma unroll
        for (int jj = 0; jj < 4; jj++) { acc1[jj][0] = 0ull; acc1[jj][1] = 0ull; }
        const float* X = Xs[slab];
        #pragma unroll 4
        for (int l = 0; l < S; l++) {
            float4 xv = ((const float4*)(X  + l * S))[tk];
            float4 gv = ((const float4*)(Gs + l * S))[tj];
            ull xp0, xp1;
            PACK2(xp0, xv.x, xv.y);
            PACK2(xp1, xv.z, xv.w);
            float ga[4] = {gv.x, gv.y, gv.z, gv.w};
            #pragma unroll
            for (int jj = 0; jj < 4; jj++) {
                ull gd; DUP2(gd, ga[jj]);
                FMA2(acc1[jj][0], gd, xp0);
                FMA2(acc1[jj][1], gd, xp1);
            }
        }
        __syncthreads();
        #pragma unroll
        for (int jj = 0; jj < 4; jj++) {
            float x0, x1, x2, x3;
            UNPK2(x0, x1, acc1[jj][0]);
            UNPK2(x2, x3, acc1[jj][1]);
            ((float4*)(Ts[slab] + (tj * 4 + jj) * S))[tk] = make_float4(x0, x1, x2, x3);
        }
        {
            const float4* gsrc = (const float4*)&d_g1t[h][0][0];
            float4* gdst = (float4*)Gs;
            for (int q = t; q < SP / 4; q += 288) gdst[q] = gsrc[q];
        }
        __syncthreads();
        ull acc2[4][2];
        #pragma unroll
        for (int jj = 0; jj < 4; jj++) { acc2[jj][0] = 0ull; acc2[jj][1] = 0ull; }
        const float* T2 = Ts[slab];
        #pragma unroll 2
        for (int k4 = 0; k4 < S / 4; k4++) {
            float tvf[4][4];
            #pragma unroll
            for (int jj = 0; jj < 4; jj++) {
                float4 tv = *(const float4*)(T2 + (tj * 4 + jj) * S + k4 * 4);
                tvf[jj][0] = tv.x; tvf[jj][1] = tv.y; tvf[jj][2] = tv.z; tvf[jj][3] = tv.w;
            }
            #pragma unroll
            for (int kk = 0; kk < 4; kk++) {
                float4 iv = ((const float4*)(Gs + (k4 * 4 + kk) * S))[tk];
                ull ip0, ip1;
                PACK2(ip0, iv.x, iv.y);
                PACK2(ip1, iv.z, iv.w);
                #pragma unroll
                for (int jj = 0; jj < 4; jj++) {
                    ull td; DUP2(td, tvf[jj][kk]);
                    FMA2(acc2[jj][0], td, ip0);
                    FMA2(acc2[jj][1], td, ip1);
                }
            }
        }
        float* Ub = &d_U[h * CH + dp * 2 + slab][(size_t)b * SP];
        #pragma unroll
        for (int jj = 0; jj < 4; jj++) {
            float x0, x1, x2, x3;
            UNPK2(x0, x1, acc2[jj][0]);
            UNPK2(x2, x3, acc2[jj][1]);
            ((float4*)(Ub + (tj * 4 + jj) * S))[tk] = make_float4(x0, x1, x2, x3);
        }
    }
}

// ---------------------------------------------------------------------------
// Stage C v2: even/odd-K paired FFMA2 GEMM (zero packing movs)
// out[b,c,j,i] = bias[c] + sum_k W[c][k] * U[k][spat]
// Block tile 128c x 128s, BK=16 (8 k-pairs). Thread tile 8c x 4s. 512 threads.
// acc[r][u] : .lo accumulates even-k, .hi odd-k; reduced in epilogue.
// Smem layouts (k-pair major, 260-float slabs for bank spread):
//   Wa[kp][cg(16)][ci(8)][ko(2)]  -> A-frag = 4x LDS.128, warp-broadcast
//   Ub[kp][ss(4)][sg(32)][ko(2)]  -> B-frag = 4x LDS.64, lane-stride 8B
// ---------------------------------------------------------------------------
#define BK    16
#define SLAB  260   // 256 floats + 4 pad
__global__ __launch_bounds__(512, 1) void k_stageC(const float* __restrict__ W,
                                                   const float* __restrict__ bias,
                                                   float* __restrict__ out) {
    __shared__ __align__(16) float Wa[8 * SLAB];
    __shared__ __align__(16) float Ub[8 * SLAB];
    int s0 = blockIdx.x * 128;
    int c0 = blockIdx.y * 128;
    int t  = threadIdx.x;
    int sc = t & 31;        // s-group: covers s = sc*4 .. sc*4+3
    int cc = t >> 5;        // c-group: covers c = cc*8 .. cc*8+7

    // loader indices
    int lc  = t >> 2;       // 0..127  (c for A staging)
    int lk4 = t & 3;        // 0..3    (float4 index within BK for A)
    int lk  = t >> 5;       // 0..15   (k for B staging)
    int ls4 = t & 31;       // 0..31   (s-group for B staging)

    const float4* W4 = (const float4*)W;
    const float4* U4 = (const float4*)&d_U[0][0];

    ull acc[8][4];
    #pragma unroll
    for (int r = 0; r < 8; r++)
        #pragma unroll
        for (int u = 0; u < 4; u++) acc[r][u] = 0ull;

    // prefetch tile 0
    float4 pa = W4[(size_t)(c0 + lc) * (HD / 4) + lk4];
    float4 pb = U4[(size_t)lk * (NSPAT / 4) + (s0 >> 2) + ls4];

    for (int tl = 0; tl < HD / BK; tl++) {
        __syncthreads();
        // store A: float4 = k (lk4*4 .. +3) for row lc -> kpairs lk4*2, lk4*2+1
        {
            float* wd0 = Wa + (lk4 * 2) * SLAB + (lc >> 3) * 16 + (lc & 7) * 2;
            float* wd1 = wd0 + SLAB;
            *(float2*)wd0 = make_float2(pa.x, pa.y);
            *(float2*)wd1 = make_float2(pa.z, pa.w);
        }
        // store B: float4 = s (ls4*4 .. +3) at k=lk -> kp = lk>>1, ko = lk&1
        {
            float* ud = Ub + (lk >> 1) * SLAB + ls4 * 2 + (lk & 1);
            ud[0 * 64] = pb.x;
            ud[1 * 64] = pb.y;
            ud[2 * 64] = pb.z;
            ud[3 * 64] = pb.w;
        }
        __syncthreads();
        // prefetch next tile
        if (tl + 1 < HD / BK) {
            int p0 = (tl + 1) * BK;
            pa = W4[(size_t)(c0 + lc) * (HD / 4) + (p0 >> 2) + lk4];
            pb = U4[(size_t)(p0 + lk) * (NSPAT / 4) + (s0 >> 2) + ls4];
        }
        // consume
        #pragma unroll
        for (int kp = 0; kp < 8; kp++) {
            const ulonglong2* ap = (const ulonglong2*)(Wa + kp * SLAB + cc * 16);
            ulonglong2 a01 = ap[0];
            ulonglong2 a23 = ap[1];
            ulonglong2 a45 = ap[2];
            ulonglong2 a67 = ap[3];
            const float* bp = Ub + kp * SLAB + sc * 2;
            ull b0 = *(const ull*)(bp + 0 * 64);
            ull b1 = *(const ull*)(bp + 1 * 64);
            ull b2 = *(const ull*)(bp + 2 * 64);
            ull b3 = *(const ull*)(bp + 3 * 64);
            ull av[8] = {a01.x, a01.y, a23.x, a23.y, a45.x, a45.y, a67.x, a67.y};
            #pragma unroll
            for (int r = 0; r < 8; r++) {
                FMA2(acc[r][0], av[r], b0);
                FMA2(acc[r][1], av[r], b1);
                FMA2(acc[r][2], av[r], b2);
                FMA2(acc[r][3], av[r], b3);
            }
        }
    }

    int b   = s0 / SP;      // tile never crosses batch (2304 = 18*128)
    int sp0 = s0 % SP;
    #pragma unroll
    for (int r = 0; r < 8; r++) {
        int c = c0 + cc * 8 + r;
        float bvl = bias[c];
        float v[4];
        #pragma unroll
        for (int u = 0; u < 4; u++) {
            float lo, hi;
            UNPK2(lo, hi, acc[r][u]);
            v[u] = lo + hi + bvl;
        }
        float* op = out + ((size_t)(b * CH + c)) * SP + sp0 + sc * 4;
        *(float4*)op = make_float4(v[0], v[1], v[2], v[3]);
    }
}

// ---------------------------------------------------------------------------
extern "C" void kernel_launch(void* const* d_in, const int* in_sizes, int n_in,
                              void* d_out, int out_size) {
    const float* hs      = (const float*)d_in[0];
    const float* centers = (const float*)d_in[1];
    const float* spreads = (const float*)d_in[2];
    const float* W       = (const float*)d_in[3];
    const float* bias    = (const float*)d_in[4];
    float* out   = (float*)d_out;
    float* probs = out + (size_t)BATCH * CH * SP;

    k_gauss  <<<(2 * NH * S + 3) / 4, 128>>>(centers, spreads);
    k_probs  <<<SP * NH, 192>>>(probs);
    k_fusedAB<<<BATCH * (CH / 2), 288>>>(hs);
    k_stageC <<<dim3(NSPAT / 128, CH / 128), 512>>>(W, bias, out);
    (void)in_sizes; (void)n_in; (void)out_size;
}

// round 6
// speedup vs baseline: 1.0469x; 1.0469x over previous
#include <cuda_runtime.h>
#include <math.h>
#include <float.h>
#include <stdint.h>

#define BATCH 8
#define CH    256
#define NH    9
#define S     48
#define SP    (S*S)        // 2304
#define HD    (NH*CH)      // 2304
#define NSPAT (BATCH*SP)   // 18432

// Scratch (static __device__ — no allocations allowed)
__device__ float d_g1 [NH][S][S];   // [h][i][k]
__device__ float d_g2 [NH][S][S];   // [h][j][l]
__device__ float d_g1t[NH][S][S];   // [h][k][i]
__device__ float d_g2t[NH][S][S];   // [h][l][j]
__device__ float d_U[HD][NSPAT];    // [hd][b*2304 + j*48 + i]

// ---------------------------------------------------------------------------
// Kernel 0: per-row 1D Gaussian softmax factors (and transposes)
// ---------------------------------------------------------------------------
__global__ void k_gauss(const float* __restrict__ centers,
                        const float* __restrict__ spreads) {
    int gw   = (blockIdx.x * blockDim.x + threadIdx.x) >> 5;
    int lane = threadIdx.x & 31;
    if (gw >= 2 * NH * S) return;
    int which = gw / (NH * S);
    int r     = gw % (NH * S);
    int h = r / S, pos = r % S;
    float sp = spreads[h];
    float a  = sp * sp;
    float mu = centers[2 * h + which];

    float dx0 = (float)(lane - pos);
    float e0  = a * (mu * dx0 - 0.5f * dx0 * dx0);
    float e1  = -FLT_MAX;
    if (lane < S - 32) {
        float dx1 = (float)(lane + 32 - pos);
        e1 = a * (mu * dx1 - 0.5f * dx1 * dx1);
    }
    float m = fmaxf(e0, e1);
    #pragma unroll
    for (int o = 16; o > 0; o >>= 1) m = fmaxf(m, __shfl_xor_sync(0xffffffffu, m, o));
    float v0 = expf(e0 - m);
    float v1 = (lane < S - 32) ? expf(e1 - m) : 0.f;
    float s = v0 + v1;
    #pragma unroll
    for (int o = 16; o > 0; o >>= 1) s += __shfl_xor_sync(0xffffffffu, s, o);
    float inv = 1.f / s;
    v0 *= inv; v1 *= inv;

    float (*g )[S] = which ? d_g2 [h] : d_g1 [h];
    float (*gt)[S] = which ? d_g2t[h] : d_g1t[h];
    g [pos][lane] = v0;
    gt[lane][pos] = v0;
    if (lane < S - 32) {
        g [pos][lane + 32] = v1;
        gt[lane + 32][pos] = v1;
    }
}

// ---------------------------------------------------------------------------
// Kernel 1: probs[i,j,h,k,l] = P1[h,i,k] * P2[h,j,l]   (pure HBM write)
// ---------------------------------------------------------------------------
__global__ __launch_bounds__(192) void k_probs(float* __restrict__ probs) {
    int blk = blockIdx.x;
    int h   = blk % NH;
    int ij  = blk / NH;
    int j = ij % S, i = ij / S;
    __shared__ float f[S];
    __shared__ float g[S];
    int t = threadIdx.x;
    if (t < S)            f[t]     = d_g1[h][i][t];
    else if (t < 2 * S)   g[t - S] = d_g2[h][j][t - S];
    __syncthreads();
    float4* outp = (float4*)(probs + (size_t)blk * SP);
    const float4* g4 = (const float4*)g;
    #pragma unroll
    for (int q = t; q < SP / 4; q += 192) {
        int k = q / 12, l4 = q % 12;
        float  fk = f[k];
        float4 gv = g4[l4];
        outp[q] = make_float4(fk * gv.x, fk * gv.y, fk * gv.z, fk * gv.w);
    }
}

// ---------------------------------------------------------------------------
// Fused stages A+B, scalar FFMA (R4 structure, R2 arithmetic):
//   stage1: T[j,k] = sum_l P2[h,j,l] * X[l,k]         (T kept in smem)
//   stage2: U[h*256+d][b*2304+j*48+i] = sum_k P1[h,i,k] * T[j,k]
// 288 thr = 2 slabs x 144 (12x12 thread grid, 4x4 tiles).
// ---------------------------------------------------------------------------
__global__ __launch_bounds__(288) void k_fusedAB(const float* __restrict__ hs) {
    __shared__ float Xs[2][SP];   // [slab][l*48 + k]
    __shared__ float Ts[2][SP];   // [slab][j*48 + k]
    __shared__ float Gs[SP];      // g2t[l*48+j] then g1t[k*48+i]
    int blk = blockIdx.x;
    int b  = blk >> 7;
    int dp = blk & 127;
    int t  = threadIdx.x;
    int slab = t / 144, tt = t % 144;
    int tk = tt % 12, tj = tt / 12;
    {
        const float4* src = (const float4*)(hs + (size_t)(b * CH + dp * 2) * SP);
        float4* dst = (float4*)&Xs[0][0];
        for (int q = t; q < 2 * SP / 4; q += 288) dst[q] = src[q];
    }
    for (int h = 0; h < NH; h++) {
        __syncthreads();   // prior-h stage2 done reading Ts/Gs
        {
            const float4* gsrc = (const float4*)&d_g2t[h][0][0];
            float4* gdst = (float4*)Gs;
            for (int q = t; q < SP / 4; q += 288) gdst[q] = gsrc[q];
        }
        __syncthreads();
        // ---- stage 1: T = P2 * X (scalar 4x4 register tile) ----
        float acc1[4][4];
        #pragma unroll
        for (int jj = 0; jj < 4; jj++)
            #pragma unroll
            for (int kk = 0; kk < 4; kk++) acc1[jj][kk] = 0.f;
        const float* X = Xs[slab];
        #pragma unroll 8
        for (int l = 0; l < S; l++) {
            float4 xv = ((const float4*)(X  + l * S))[tk];
            float4 gv = ((const float4*)(Gs + l * S))[tj];
            float xa[4] = {xv.x, xv.y, xv.z, xv.w};
            float ga[4] = {gv.x, gv.y, gv.z, gv.w};
            #pragma unroll
            for (int jj = 0; jj < 4; jj++)
                #pragma unroll
                for (int kk = 0; kk < 4; kk++)
                    acc1[jj][kk] = fmaf(ga[jj], xa[kk], acc1[jj][kk]);
        }
        __syncthreads();   // stage1 reads of Gs complete before Gs reload
        // write T tile (row-major [j][k]) + load g1t
        #pragma unroll
        for (int jj = 0; jj < 4; jj++) {
            ((float4*)(Ts[slab] + (tj * 4 + jj) * S))[tk] =
                make_float4(acc1[jj][0], acc1[jj][1], acc1[jj][2], acc1[jj][3]);
        }
        {
            const float4* gsrc = (const float4*)&d_g1t[h][0][0];
            float4* gdst = (float4*)Gs;
            for (int q = t; q < SP / 4; q += 288) gdst[q] = gsrc[q];
        }
        __syncthreads();
        // ---- stage 2: U = T * P1^T (scalar 4x4 register tile) ----
        float acc2[4][4];
        #pragma unroll
        for (int jj = 0; jj < 4; jj++)
            #pragma unroll
            for (int ii = 0; ii < 4; ii++) acc2[jj][ii] = 0.f;
        const float* T2 = Ts[slab];
        #pragma unroll 2
        for (int k4 = 0; k4 < S / 4; k4++) {
            float tvf[4][4];
            #pragma unroll
            for (int jj = 0; jj < 4; jj++) {
                float4 tv = *(const float4*)(T2 + (tj * 4 + jj) * S + k4 * 4);
                tvf[jj][0] = tv.x; tvf[jj][1] = tv.y; tvf[jj][2] = tv.z; tvf[jj][3] = tv.w;
            }
            #pragma unroll
            for (int kk = 0; kk < 4; kk++) {
                float4 iv = ((const float4*)(Gs + (k4 * 4 + kk) * S))[tk];
                float ia[4] = {iv.x, iv.y, iv.z, iv.w};
                #pragma unroll
                for (int jj = 0; jj < 4; jj++) {
                    float tb = tvf[jj][kk];
                    #pragma unroll
                    for (int ii = 0; ii < 4; ii++)
                        acc2[jj][ii] = fmaf(tb, ia[ii], acc2[jj][ii]);
                }
            }
        }
        float* Ub = &d_U[h * CH + dp * 2 + slab][(size_t)b * SP];
        #pragma unroll
        for (int jj = 0; jj < 4; jj++) {
            ((float4*)(Ub + (tj * 4 + jj) * S))[tk] =
                make_float4(acc2[jj][0], acc2[jj][1], acc2[jj][2], acc2[jj][3]);
        }
    }
}

// ---------------------------------------------------------------------------
// Stage C (R2 scalar version — measured best):
// out[b,c,j,i] = bias[c] + sum_hd W[c][hd] * U[hd][spat]
// GEMM M=256, N=18432, K=2304. 128x128x16 tile, 8x8/thread, 256 threads.
// ---------------------------------------------------------------------------
#define BK 16
__global__ __launch_bounds__(256) void k_stageC(const float* __restrict__ W,
                                                const float* __restrict__ bias,
                                                float* __restrict__ out) {
    __shared__ float Ws[BK][128];   // [p][c]   (transposed from W)
    __shared__ float Us[BK][128];   // [p][s]
    int s0 = blockIdx.x * 128;
    int c0 = blockIdx.y * 128;
    int t  = threadIdx.x;
    int tc = t & 15, ts = t >> 4;
    float acc[8][8];
    #pragma unroll
    for (int r = 0; r < 8; r++)
        #pragma unroll
        for (int u = 0; u < 8; u++) acc[r][u] = 0.f;

    const float4* W4     = (const float4*)W;
    const float4* U4base = (const float4*)&d_U[0][0];

    for (int p0 = 0; p0 < HD; p0 += BK) {
        __syncthreads();
        #pragma unroll
        for (int q = t; q < 512; q += 256) {
            int c = q >> 2, p4 = q & 3;
            float4 v = W4[(size_t)(c0 + c) * (HD / 4) + (p0 >> 2) + p4];
            Ws[p4 * 4 + 0][c] = v.x;
            Ws[p4 * 4 + 1][c] = v.y;
            Ws[p4 * 4 + 2][c] = v.z;
            Ws[p4 * 4 + 3][c] = v.w;
        }
        #pragma unroll
        for (int q = t; q < 512; q += 256) {
            int k = q >> 5, s4 = q & 31;
            ((float4*)Us[k])[s4] = U4base[(size_t)(p0 + k) * (NSPAT / 4) + (s0 >> 2) + s4];
        }
        __syncthreads();
        #pragma unroll
        for (int k = 0; k < BK; k++) {
            float4 a0 = ((const float4*)Ws[k])[tc];
            float4 a1 = ((const float4*)Ws[k])[16 + tc];
            float4 b0 = ((const float4*)Us[k])[ts];
            float4 b1 = ((const float4*)Us[k])[16 + ts];
            float av[8] = {a0.x, a0.y, a0.z, a0.w, a1.x, a1.y, a1.z, a1.w};
            float bv[8] = {b0.x, b0.y, b0.z, b0.w, b1.x, b1.y, b1.z, b1.w};
            #pragma unroll
            for (int r = 0; r < 8; r++)
                #pragma unroll
                for (int u = 0; u < 8; u++)
                    acc[r][u] = fmaf(av[r], bv[u], acc[r][u]);
        }
    }

    int b   = s0 / SP;      // tile never crosses batch (2304 = 18*128)
    int sp0 = s0 % SP;
    #pragma unroll
    for (int r = 0; r < 8; r++) {
        int c = c0 + (r >> 2) * 64 + tc * 4 + (r & 3);
        float bvl = bias[c];
        float* op = out + ((size_t)(b * CH + c)) * SP + sp0;
        #pragma unroll
        for (int sh = 0; sh < 2; sh++) {
            int sb = sh * 64 + ts * 4;
            float4 v = make_float4(acc[r][sh * 4 + 0] + bvl,
                                   acc[r][sh * 4 + 1] + bvl,
                                   acc[r][sh * 4 + 2] + bvl,
                                   acc[r][sh * 4 + 3] + bvl);
            *(float4*)(op + sb) = v;
        }
    }
}

// ---------------------------------------------------------------------------
extern "C" void kernel_launch(void* const* d_in, const int* in_sizes, int n_in,
                              void* d_out, int out_size) {
    const float* hs      = (const float*)d_in[0];
    const float* centers = (const float*)d_in[1];
    const float* spreads = (const float*)d_in[2];
    const float* W       = (const float*)d_in[3];
    const float* bias    = (const float*)d_in[4];
    float* out   = (float*)d_out;
    float* probs = out + (size_t)BATCH * CH * SP;

    k_gauss  <<<(2 * NH * S + 3) / 4, 128>>>(centers, spreads);
    k_probs  <<<SP * NH, 192>>>(probs);
    k_fusedAB<<<BATCH * (CH / 2), 288>>>(hs);
    k_stageC <<<dim3(NSPAT / 128, CH / 128), 256>>>(W, bias, out);
    (void)in_sizes; (void)n_in; (void)out_size;
}

// round 7
// speedup vs baseline: 1.1088x; 1.0591x over previous
#include <cuda_runtime.h>
#include <math.h>
#include <float.h>
#include <stdint.h>

#define BATCH 8
#define CH    256
#define NH    9
#define S     48
#define SP    (S*S)        // 2304
#define HD    (NH*CH)      // 2304
#define NSPAT (BATCH*SP)   // 18432

// Scratch (static __device__ — no allocations allowed)
__device__ float d_g1 [NH][S][S];   // [h][i][k]
__device__ float d_g2 [NH][S][S];   // [h][j][l]
__device__ float d_g1t[NH][S][S];   // [h][k][i]
__device__ float d_g2t[NH][S][S];   // [h][l][j]
__device__ float d_U[HD][NSPAT];    // [hd][b*2304 + j*48 + i]

// ---------------------------------------------------------------------------
// Kernel 0: per-row 1D Gaussian softmax factors (and transposes)
// ---------------------------------------------------------------------------
__global__ void k_gauss(const float* __restrict__ centers,
                        const float* __restrict__ spreads) {
    int gw   = (blockIdx.x * blockDim.x + threadIdx.x) >> 5;
    int lane = threadIdx.x & 31;
    if (gw >= 2 * NH * S) return;
    int which = gw / (NH * S);
    int r     = gw % (NH * S);
    int h = r / S, pos = r % S;
    float sp = spreads[h];
    float a  = sp * sp;
    float mu = centers[2 * h + which];

    float dx0 = (float)(lane - pos);
    float e0  = a * (mu * dx0 - 0.5f * dx0 * dx0);
    float e1  = -FLT_MAX;
    if (lane < S - 32) {
        float dx1 = (float)(lane + 32 - pos);
        e1 = a * (mu * dx1 - 0.5f * dx1 * dx1);
    }
    float m = fmaxf(e0, e1);
    #pragma unroll
    for (int o = 16; o > 0; o >>= 1) m = fmaxf(m, __shfl_xor_sync(0xffffffffu, m, o));
    float v0 = expf(e0 - m);
    float v1 = (lane < S - 32) ? expf(e1 - m) : 0.f;
    float s = v0 + v1;
    #pragma unroll
    for (int o = 16; o > 0; o >>= 1) s += __shfl_xor_sync(0xffffffffu, s, o);
    float inv = 1.f / s;
    v0 *= inv; v1 *= inv;

    float (*g )[S] = which ? d_g2 [h] : d_g1 [h];
    float (*gt)[S] = which ? d_g2t[h] : d_g1t[h];
    g [pos][lane] = v0;
    gt[lane][pos] = v0;
    if (lane < S - 32) {
        g [pos][lane + 32] = v1;
        gt[lane + 32][pos] = v1;
    }
}

// ---------------------------------------------------------------------------
// Kernel 1: probs[i,j,h,k,l] = P1[h,i,k] * P2[h,j,l]   (pure HBM write)
// ---------------------------------------------------------------------------
__global__ __launch_bounds__(192) void k_probs(float* __restrict__ probs) {
    int blk = blockIdx.x;
    int h   = blk % NH;
    int ij  = blk / NH;
    int j = ij % S, i = ij / S;
    __shared__ float f[S];
    __shared__ float g[S];
    int t = threadIdx.x;
    if (t < S)            f[t]     = d_g1[h][i][t];
    else if (t < 2 * S)   g[t - S] = d_g2[h][j][t - S];
    __syncthreads();
    float4* outp = (float4*)(probs + (size_t)blk * SP);
    const float4* g4 = (const float4*)g;
    #pragma unroll
    for (int q = t; q < SP / 4; q += 192) {
        int k = q / 12, l4 = q % 12;
        float  fk = f[k];
        float4 gv = g4[l4];
        outp[q] = make_float4(fk * gv.x, fk * gv.y, fk * gv.z, fk * gv.w);
    }
}

// ---------------------------------------------------------------------------
// Fused stages A+B, scalar FFMA, 3 syncs/head (separate G1s/G2s buffers):
//   stage1: T[j,k] = sum_l P2[h,j,l] * X[l,k]         (T kept in smem)
//   stage2: U[h*256+d][b*2304+j*48+i] = sum_k P1[h,i,k] * T[j,k]
// 288 thr = 2 slabs x 144 (12x12 thread grid, 4x4 tiles).
// ---------------------------------------------------------------------------
__global__ __launch_bounds__(288) void k_fusedAB(const float* __restrict__ hs) {
    __shared__ float Xs[2][SP];   // [slab][l*48 + k]
    __shared__ float Ts[2][SP];   // [slab][j*48 + k]
    __shared__ float G2s[SP];     // g2t[l*48 + j]
    __shared__ float G1s[SP];     // g1t[k*48 + i]
    int blk = blockIdx.x;
    int b  = blk >> 7;
    int dp = blk & 127;
    int t  = threadIdx.x;
    int slab = t / 144, tt = t % 144;
    int tk = tt % 12, tj = tt / 12;
    {
        const float4* src = (const float4*)(hs + (size_t)(b * CH + dp * 2) * SP);
        float4* dst = (float4*)&Xs[0][0];
        for (int q = t; q < 2 * SP / 4; q += 288) dst[q] = src[q];
    }
    for (int h = 0; h < NH; h++) {
        __syncthreads();   // prior-h stage2 done reading Ts/G1s, stage1 done with G2s
        {
            const float4* g2src = (const float4*)&d_g2t[h][0][0];
            const float4* g1src = (const float4*)&d_g1t[h][0][0];
            float4* g2dst = (float4*)G2s;
            float4* g1dst = (float4*)G1s;
            for (int q = t; q < SP / 4; q += 288) {
                g2dst[q] = g2src[q];
                g1dst[q] = g1src[q];
            }
        }
        __syncthreads();
        // ---- stage 1: T = P2 * X (scalar 4x4 register tile) ----
        float acc1[4][4];
        #pragma unroll
        for (int jj = 0; jj < 4; jj++)
            #pragma unroll
            for (int kk = 0; kk < 4; kk++) acc1[jj][kk] = 0.f;
        const float* X = Xs[slab];
        #pragma unroll 8
        for (int l = 0; l < S; l++) {
            float4 xv = ((const float4*)(X   + l * S))[tk];
            float4 gv = ((const float4*)(G2s + l * S))[tj];
            float xa[4] = {xv.x, xv.y, xv.z, xv.w};
            float ga[4] = {gv.x, gv.y, gv.z, gv.w};
            #pragma unroll
            for (int jj = 0; jj < 4; jj++)
                #pragma unroll
                for (int kk = 0; kk < 4; kk++)
                    acc1[jj][kk] = fmaf(ga[jj], xa[kk], acc1[jj][kk]);
        }
        // write T tile (prior-h readers finished before top sync)
        #pragma unroll
        for (int jj = 0; jj < 4; jj++) {
            ((float4*)(Ts[slab] + (tj * 4 + jj) * S))[tk] =
                make_float4(acc1[jj][0], acc1[jj][1], acc1[jj][2], acc1[jj][3]);
        }
        __syncthreads();
        // ---- stage 2: U = T * P1^T (scalar 4x4 register tile) ----
        float acc2[4][4];
        #pragma unroll
        for (int jj = 0; jj < 4; jj++)
            #pragma unroll
            for (int ii = 0; ii < 4; ii++) acc2[jj][ii] = 0.f;
        const float* T2 = Ts[slab];
        #pragma unroll 2
        for (int k4 = 0; k4 < S / 4; k4++) {
            float tvf[4][4];
            #pragma unroll
            for (int jj = 0; jj < 4; jj++) {
                float4 tv = *(const float4*)(T2 + (tj * 4 + jj) * S + k4 * 4);
                tvf[jj][0] = tv.x; tvf[jj][1] = tv.y; tvf[jj][2] = tv.z; tvf[jj][3] = tv.w;
            }
            #pragma unroll
            for (int kk = 0; kk < 4; kk++) {
                float4 iv = ((const float4*)(G1s + (k4 * 4 + kk) * S))[tk];
                float ia[4] = {iv.x, iv.y, iv.z, iv.w};
                #pragma unroll
                for (int jj = 0; jj < 4; jj++) {
                    float tb = tvf[jj][kk];
                    #pragma unroll
                    for (int ii = 0; ii < 4; ii++)
                        acc2[jj][ii] = fmaf(tb, ia[ii], acc2[jj][ii]);
                }
            }
        }
        float* Ub = &d_U[h * CH + dp * 2 + slab][(size_t)b * SP];
        #pragma unroll
        for (int jj = 0; jj < 4; jj++) {
            ((float4*)(Ub + (tj * 4 + jj) * S))[tk] =
                make_float4(acc2[jj][0], acc2[jj][1], acc2[jj][2], acc2[jj][3]);
        }
    }
}

// ---------------------------------------------------------------------------
// Stage C: out[b,c,j,i] = bias[c] + sum_hd W[c][hd] * U[hd][spat]
// GEMM M=256, N=18432, K=2304. 128x128x16 tile, 8x8/thread, 256 threads.
// Double-buffered smem + register prefetch: ONE sync per K-tile.
// ---------------------------------------------------------------------------
#define BK 16
__global__ __launch_bounds__(256, 2) void k_stageC(const float* __restrict__ W,
                                                   const float* __restrict__ bias,
                                                   float* __restrict__ out) {
    __shared__ float Ws[2][BK][128];   // [buf][p][c]
    __shared__ float Us[2][BK][128];   // [buf][p][s]
    int s0 = blockIdx.x * 128;
    int c0 = blockIdx.y * 128;
    int t  = threadIdx.x;
    int tc = t & 15, ts = t >> 4;

    // loader indices
    int lcA = t >> 2;        // 0..63  (A row; +64 for second)
    int lp4 = t & 3;         // 0..3   (float4 index within BK)
    int lkB = t >> 5;        // 0..7   (B k; +8 for second)
    int ls4 = t & 31;        // 0..31  (B s-group)

    float acc[8][8];
    #pragma unroll
    for (int r = 0; r < 8; r++)
        #pragma unroll
        for (int u = 0; u < 8; u++) acc[r][u] = 0.f;

    const float4* W4 = (const float4*)W;
    const float4* U4 = (const float4*)&d_U[0][0];

    float4 pa0, pa1, pb0, pb1;
    // prefetch tile 0
    pa0 = W4[(size_t)(c0 + lcA)      * (HD / 4) + lp4];
    pa1 = W4[(size_t)(c0 + lcA + 64) * (HD / 4) + lp4];
    pb0 = U4[(size_t)(lkB)     * (NSPAT / 4) + (s0 >> 2) + ls4];
    pb1 = U4[(size_t)(lkB + 8) * (NSPAT / 4) + (s0 >> 2) + ls4];
    // store tile 0 -> buf 0
    {
        Ws[0][lp4 * 4 + 0][lcA] = pa0.x;
        Ws[0][lp4 * 4 + 1][lcA] = pa0.y;
        Ws[0][lp4 * 4 + 2][lcA] = pa0.z;
        Ws[0][lp4 * 4 + 3][lcA] = pa0.w;
        Ws[0][lp4 * 4 + 0][lcA + 64] = pa1.x;
        Ws[0][lp4 * 4 + 1][lcA + 64] = pa1.y;
        Ws[0][lp4 * 4 + 2][lcA + 64] = pa1.z;
        Ws[0][lp4 * 4 + 3][lcA + 64] = pa1.w;
        ((float4*)Us[0][lkB])[ls4]     = pb0;
        ((float4*)Us[0][lkB + 8])[ls4] = pb1;
    }
    __syncthreads();

    #define NTILES (HD / BK)
    for (int tl = 0; tl < NTILES; tl++) {
        int buf = tl & 1;
        // prefetch next tile (global -> regs), latency hidden by compute below
        if (tl + 1 < NTILES) {
            int p0 = (tl + 1) * BK;
            pa0 = W4[(size_t)(c0 + lcA)      * (HD / 4) + (p0 >> 2) + lp4];
            pa1 = W4[(size_t)(c0 + lcA + 64) * (HD / 4) + (p0 >> 2) + lp4];
            pb0 = U4[(size_t)(p0 + lkB)     * (NSPAT / 4) + (s0 >> 2) + ls4];
            pb1 = U4[(size_t)(p0 + lkB + 8) * (NSPAT / 4) + (s0 >> 2) + ls4];
        }
        // compute on current buffer
        #pragma unroll
        for (int k = 0; k < BK; k++) {
            float4 a0 = ((const float4*)Ws[buf][k])[tc];
            float4 a1 = ((const float4*)Ws[buf][k])[16 + tc];
            float4 b0 = ((const float4*)Us[buf][k])[ts];
            float4 b1 = ((const float4*)Us[buf][k])[16 + ts];
            float av[8] = {a0.x, a0.y, a0.z, a0.w, a1.x, a1.y, a1.z, a1.w};
            float bv[8] = {b0.x, b0.y, b0.z, b0.w, b1.x, b1.y, b1.z, b1.w};
            #pragma unroll
            for (int r = 0; r < 8; r++)
                #pragma unroll
                for (int u = 0; u < 8; u++)
                    acc[r][u] = fmaf(av[r], bv[u], acc[r][u]);
        }
        // stage prefetched tile into the other buffer
        if (tl + 1 < NTILES) {
            int nb = buf ^ 1;
            Ws[nb][lp4 * 4 + 0][lcA] = pa0.x;
            Ws[nb][lp4 * 4 + 1][lcA] = pa0.y;
            Ws[nb][lp4 * 4 + 2][lcA] = pa0.z;
            Ws[nb][lp4 * 4 + 3][lcA] = pa0.w;
            Ws[nb][lp4 * 4 + 0][lcA + 64] = pa1.x;
            Ws[nb][lp4 * 4 + 1][lcA + 64] = pa1.y;
            Ws[nb][lp4 * 4 + 2][lcA + 64] = pa1.z;
            Ws[nb][lp4 * 4 + 3][lcA + 64] = pa1.w;
            ((float4*)Us[nb][lkB])[ls4]     = pb0;
            ((float4*)Us[nb][lkB + 8])[ls4] = pb1;
        }
        __syncthreads();
    }

    int b   = s0 / SP;      // tile never crosses batch (2304 = 18*128)
    int sp0 = s0 % SP;
    #pragma unroll
    for (int r = 0; r < 8; r++) {
        int c = c0 + (r >> 2) * 64 + tc * 4 + (r & 3);
        float bvl = bias[c];
        float* op = out + ((size_t)(b * CH + c)) * SP + sp0;
        #pragma unroll
        for (int sh = 0; sh < 2; sh++) {
            int sb = sh * 64 + ts * 4;
            float4 v = make_float4(acc[r][sh * 4 + 0] + bvl,
                                   acc[r][sh * 4 + 1] + bvl,
                                   acc[r][sh * 4 + 2] + bvl,
                                   acc[r][sh * 4 + 3] + bvl);
            *(float4*)(op + sb) = v;
        }
    }
}

// ---------------------------------------------------------------------------
extern "C" void kernel_launch(void* const* d_in, const int* in_sizes, int n_in,
                              void* d_out, int out_size) {
    const float* hs      = (const float*)d_in[0];
    const float* centers = (const float*)d_in[1];
    const float* spreads = (const float*)d_in[2];
    const float* W       = (const float*)d_in[3];
    const float* bias    = (const float*)d_in[4];
    float* out   = (float*)d_out;
    float* probs = out + (size_t)BATCH * CH * SP;

    k_gauss  <<<(2 * NH * S + 3) / 4, 128>>>(centers, spreads);
    k_probs  <<<SP * NH, 192>>>(probs);
    k_fusedAB<<<BATCH * (CH / 2), 288>>>(hs);
    k_stageC <<<dim3(NSPAT / 128, CH / 128), 256>>>(W, bias, out);
    (void)in_sizes; (void)n_in; (void)out_size;
}

// round 8
// speedup vs baseline: 1.1313x; 1.0203x over previous
#include <cuda_runtime.h>
#include <math.h>
#include <float.h>
#include <stdint.h>

#define BATCH 8
#define CH    256
#define NH    9
#define S     48
#define SP    (S*S)        // 2304
#define HD    (NH*CH)      // 2304
#define NSPAT (BATCH*SP)   // 18432

// Scratch (static __device__ — no allocations allowed)
__device__ float d_g1 [NH][S][S];   // [h][i][k]
__device__ float d_g2 [NH][S][S];   // [h][j][l]
__device__ float d_g1t[NH][S][S];   // [h][k][i]
__device__ float d_g2t[NH][S][S];   // [h][l][j]
__device__ float d_U[HD][NSPAT];    // [hd][b*2304 + j*48 + i]
__device__ float d_Wt[HD][CH];      // W transposed: [k][c]

__device__ __forceinline__ uint32_t smem_u32(const void* p) {
    uint32_t a;
    asm("{ .reg .u64 t; cvta.to.shared.u64 t, %1; cvt.u32.u64 %0, t; }" : "=r"(a) : "l"(p));
    return a;
}

// ---------------------------------------------------------------------------
// Kernel 0: per-row 1D Gaussian softmax factors (and transposes)
// ---------------------------------------------------------------------------
__global__ void k_gauss(const float* __restrict__ centers,
                        const float* __restrict__ spreads) {
    int gw   = (blockIdx.x * blockDim.x + threadIdx.x) >> 5;
    int lane = threadIdx.x & 31;
    if (gw >= 2 * NH * S) return;
    int which = gw / (NH * S);
    int r     = gw % (NH * S);
    int h = r / S, pos = r % S;
    float sp = spreads[h];
    float a  = sp * sp;
    float mu = centers[2 * h + which];

    float dx0 = (float)(lane - pos);
    float e0  = a * (mu * dx0 - 0.5f * dx0 * dx0);
    float e1  = -FLT_MAX;
    if (lane < S - 32) {
        float dx1 = (float)(lane + 32 - pos);
        e1 = a * (mu * dx1 - 0.5f * dx1 * dx1);
    }
    float m = fmaxf(e0, e1);
    #pragma unroll
    for (int o = 16; o > 0; o >>= 1) m = fmaxf(m, __shfl_xor_sync(0xffffffffu, m, o));
    float v0 = expf(e0 - m);
    float v1 = (lane < S - 32) ? expf(e1 - m) : 0.f;
    float s = v0 + v1;
    #pragma unroll
    for (int o = 16; o > 0; o >>= 1) s += __shfl_xor_sync(0xffffffffu, s, o);
    float inv = 1.f / s;
    v0 *= inv; v1 *= inv;

    float (*g )[S] = which ? d_g2 [h] : d_g1 [h];
    float (*gt)[S] = which ? d_g2t[h] : d_g1t[h];
    g [pos][lane] = v0;
    gt[lane][pos] = v0;
    if (lane < S - 32) {
        g [pos][lane + 32] = v1;
        gt[lane + 32][pos] = v1;
    }
}

// ---------------------------------------------------------------------------
// Kernel 0b: transpose W[c][k] -> d_Wt[k][c]
// ---------------------------------------------------------------------------
__global__ void k_wt(const float* __restrict__ W) {
    __shared__ float s[32][33];
    int k0 = blockIdx.x * 32, c0 = blockIdx.y * 32;
    int tx = threadIdx.x, ty = threadIdx.y;   // 32 x 8
    #pragma unroll
    for (int r = 0; r < 32; r += 8)
        s[ty + r][tx] = W[(size_t)(c0 + ty + r) * HD + k0 + tx];
    __syncthreads();
    #pragma unroll
    for (int r = 0; r < 32; r += 8)
        d_Wt[k0 + ty + r][c0 + tx] = s[tx][ty + r];
}

// ---------------------------------------------------------------------------
// Kernel 1: probs[i,j,h,k,l] = P1[h,i,k] * P2[h,j,l]   (pure HBM write)
// ---------------------------------------------------------------------------
__global__ __launch_bounds__(192) void k_probs(float* __restrict__ probs) {
    int blk = blockIdx.x;
    int h   = blk % NH;
    int ij  = blk / NH;
    int j = ij % S, i = ij / S;
    __shared__ float f[S];
    __shared__ float g[S];
    int t = threadIdx.x;
    if (t < S)            f[t]     = d_g1[h][i][t];
    else if (t < 2 * S)   g[t - S] = d_g2[h][j][t - S];
    __syncthreads();
    float4* outp = (float4*)(probs + (size_t)blk * SP);
    const float4* g4 = (const float4*)g;
    #pragma unroll
    for (int q = t; q < SP / 4; q += 192) {
        int k = q / 12, l4 = q % 12;
        float  fk = f[k];
        float4 gv = g4[l4];
        outp[q] = make_float4(fk * gv.x, fk * gv.y, fk * gv.z, fk * gv.w);
    }
}

// ---------------------------------------------------------------------------
// Fused stages A+B, scalar FFMA, 3 syncs/head (unchanged from R7 — validated)
// ---------------------------------------------------------------------------
__global__ __launch_bounds__(288) void k_fusedAB(const float* __restrict__ hs) {
    __shared__ float Xs[2][SP];   // [slab][l*48 + k]
    __shared__ float Ts[2][SP];   // [slab][j*48 + k]
    __shared__ float G2s[SP];     // g2t[l*48 + j]
    __shared__ float G1s[SP];     // g1t[k*48 + i]
    int blk = blockIdx.x;
    int b  = blk >> 7;
    int dp = blk & 127;
    int t  = threadIdx.x;
    int slab = t / 144, tt = t % 144;
    int tk = tt % 12, tj = tt / 12;
    {
        const float4* src = (const float4*)(hs + (size_t)(b * CH + dp * 2) * SP);
        float4* dst = (float4*)&Xs[0][0];
        for (int q = t; q < 2 * SP / 4; q += 288) dst[q] = src[q];
    }
    for (int h = 0; h < NH; h++) {
        __syncthreads();
        {
            const float4* g2src = (const float4*)&d_g2t[h][0][0];
            const float4* g1src = (const float4*)&d_g1t[h][0][0];
            float4* g2dst = (float4*)G2s;
            float4* g1dst = (float4*)G1s;
            for (int q = t; q < SP / 4; q += 288) {
                g2dst[q] = g2src[q];
                g1dst[q] = g1src[q];
            }
        }
        __syncthreads();
        float acc1[4][4];
        #pragma unroll
        for (int jj = 0; jj < 4; jj++)
            #pragma unroll
            for (int kk = 0; kk < 4; kk++) acc1[jj][kk] = 0.f;
        const float* X = Xs[slab];
        #pragma unroll 8
        for (int l = 0; l < S; l++) {
            float4 xv = ((const float4*)(X   + l * S))[tk];
            float4 gv = ((const float4*)(G2s + l * S))[tj];
            float xa[4] = {xv.x, xv.y, xv.z, xv.w};
            float ga[4] = {gv.x, gv.y, gv.z, gv.w};
            #pragma unroll
            for (int jj = 0; jj < 4; jj++)
                #pragma unroll
                for (int kk = 0; kk < 4; kk++)
                    acc1[jj][kk] = fmaf(ga[jj], xa[kk], acc1[jj][kk]);
        }
        #pragma unroll
        for (int jj = 0; jj < 4; jj++) {
            ((float4*)(Ts[slab] + (tj * 4 + jj) * S))[tk] =
                make_float4(acc1[jj][0], acc1[jj][1], acc1[jj][2], acc1[jj][3]);
        }
        __syncthreads();
        float acc2[4][4];
        #pragma unroll
        for (int jj = 0; jj < 4; jj++)
            #pragma unroll
            for (int ii = 0; ii < 4; ii++) acc2[jj][ii] = 0.f;
        const float* T2 = Ts[slab];
        #pragma unroll 2
        for (int k4 = 0; k4 < S / 4; k4++) {
            float tvf[4][4];
            #pragma unroll
            for (int jj = 0; jj < 4; jj++) {
                float4 tv = *(const float4*)(T2 + (tj * 4 + jj) * S + k4 * 4);
                tvf[jj][0] = tv.x; tvf[jj][1] = tv.y; tvf[jj][2] = tv.z; tvf[jj][3] = tv.w;
            }
            #pragma unroll
            for (int kk = 0; kk < 4; kk++) {
                float4 iv = ((const float4*)(G1s + (k4 * 4 + kk) * S))[tk];
                float ia[4] = {iv.x, iv.y, iv.z, iv.w};
                #pragma unroll
                for (int jj = 0; jj < 4; jj++) {
                    float tb = tvf[jj][kk];
                    #pragma unroll
                    for (int ii = 0; ii < 4; ii++)
                        acc2[jj][ii] = fmaf(tb, ia[ii], acc2[jj][ii]);
                }
            }
        }
        float* Ub = &d_U[h * CH + dp * 2 + slab][(size_t)b * SP];
        #pragma unroll
        for (int jj = 0; jj < 4; jj++) {
            ((float4*)(Ub + (tj * 4 + jj) * S))[tk] =
                make_float4(acc2[jj][0], acc2[jj][1], acc2[jj][2], acc2[jj][3]);
        }
    }
}

// ---------------------------------------------------------------------------
// Stage C v3: cp.async 3-stage pipeline, both operands k-major row slices.
// out[b,c,j,i] = bias[c] + sum_k Wt[k][c] * U[k][spat]
// GEMM M=256, N=18432, K=2304. 128x128x16 tile, 8x8/thread, 256 threads.
// ---------------------------------------------------------------------------
#define BK     16
#define PIPE   3
#define NTILES (HD / BK)
__global__ __launch_bounds__(256, 2) void k_stageC(const float* __restrict__ bias,
                                                   float* __restrict__ out) {
    __shared__ __align__(16) float Ws[PIPE][BK][128];   // [st][k][c]
    __shared__ __align__(16) float Us[PIPE][BK][128];   // [st][k][s]
    int s0 = blockIdx.x * 128;
    int c0 = blockIdx.y * 128;
    int t  = threadIdx.x;
    int tc = t & 15, ts = t >> 4;

    float acc[8][8];
    #pragma unroll
    for (int r = 0; r < 8; r++)
        #pragma unroll
        for (int u = 0; u < 8; u++) acc[r][u] = 0.f;

    // tile loader: 512 float4 per operand, 2 per thread each
    auto load_tile = [&](int tl, int st) {
        int k0 = tl * BK;
        #pragma unroll
        for (int i = 0; i < 2; i++) {
            int q   = t + 256 * i;
            int row = q >> 5, c4 = (q & 31) * 4;
            uint32_t wdst = smem_u32(&Ws[st][row][c4]);
            uint32_t udst = smem_u32(&Us[st][row][c4]);
            const float* wsrc = &d_Wt[k0 + row][c0 + c4];
            const float* usrc = &d_U [k0 + row][s0 + c4];
            asm volatile("cp.async.ca.shared.global [%0], [%1], 16;" :: "r"(wdst), "l"(wsrc) : "memory");
            asm volatile("cp.async.cg.shared.global [%0], [%1], 16;" :: "r"(udst), "l"(usrc) : "memory");
        }
        asm volatile("cp.async.commit_group;" ::: "memory");
    };

    load_tile(0, 0);
    load_tile(1, 1);

    for (int tl = 0; tl < NTILES; tl++) {
        int st = tl % PIPE;
        asm volatile("cp.async.wait_group 1;" ::: "memory");
        __syncthreads();
        if (tl + 2 < NTILES) load_tile(tl + 2, (tl + 2) % PIPE);
        #pragma unroll
        for (int k = 0; k < BK; k++) {
            float4 a0 = ((const float4*)Ws[st][k])[tc];
            float4 a1 = ((const float4*)Ws[st][k])[16 + tc];
            float4 b0 = ((const float4*)Us[st][k])[ts];
            float4 b1 = ((const float4*)Us[st][k])[16 + ts];
            float av[8] = {a0.x, a0.y, a0.z, a0.w, a1.x, a1.y, a1.z, a1.w};
            float bv[8] = {b0.x, b0.y, b0.z, b0.w, b1.x, b1.y, b1.z, b1.w};
            #pragma unroll
            for (int r = 0; r < 8; r++)
                #pragma unroll
                for (int u = 0; u < 8; u++)
                    acc[r][u] = fmaf(av[r], bv[u], acc[r][u]);
        }
    }

    int b   = s0 / SP;      // tile never crosses batch (2304 = 18*128)
    int sp0 = s0 % SP;
    #pragma unroll
    for (int r = 0; r < 8; r++) {
        int c = c0 + (r >> 2) * 64 + tc * 4 + (r & 3);
        float bvl = bias[c];
        float* op = out + ((size_t)(b * CH + c)) * SP + sp0;
        #pragma unroll
        for (int sh = 0; sh < 2; sh++) {
            int sb = sh * 64 + ts * 4;
            float4 v = make_float4(acc[r][sh * 4 + 0] + bvl,
                                   acc[r][sh * 4 + 1] + bvl,
                                   acc[r][sh * 4 + 2] + bvl,
                                   acc[r][sh * 4 + 3] + bvl);
            *(float4*)(op + sb) = v;
        }
    }
}

// ---------------------------------------------------------------------------
extern "C" void kernel_launch(void* const* d_in, const int* in_sizes, int n_in,
                              void* d_out, int out_size) {
    const float* hs      = (const float*)d_in[0];
    const float* centers = (const float*)d_in[1];
    const float* spreads = (const float*)d_in[2];
    const float* W       = (const float*)d_in[3];
    const float* bias    = (const float*)d_in[4];
    float* out   = (float*)d_out;
    float* probs = out + (size_t)BATCH * CH * SP;

    k_gauss  <<<(2 * NH * S + 3) / 4, 128>>>(centers, spreads);
    k_wt     <<<dim3(HD / 32, CH / 32), dim3(32, 8)>>>(W);
    k_probs  <<<SP * NH, 192>>>(probs);
    k_fusedAB<<<BATCH * (CH / 2), 288>>>(hs);
    k_stageC <<<dim3(NSPAT / 128, CH / 128), 256>>>(bias, out);
    (void)in_sizes; (void)n_in; (void)out_size;
}